// round 1
// baseline (speedup 1.0000x reference)
#include <cuda_runtime.h>
#include <math.h>

#define TPB 128
#define F_OUT 512

// Global accumulators: [0..31] = weighted h2 sum, [32]=S0, [33]=sum p*log p (dim0),
// [34]=S1, [35]=sum p*log p (dim1)
__device__ float g_acc[36];

__global__ void ph_zero() {
    if (threadIdx.x < 36) g_acc[threadIdx.x] = 0.0f;
}

// MLP front: x(2) -> 64 (relu) -> 32 (relu), accumulate w * h2 into acc[32].
template <bool USE_X0>
__device__ __forceinline__ void mlp_accum(
    float x0, float x1, float w,
    const float* __restrict__ sW1, const float* __restrict__ sB1,
    const float4* __restrict__ sW2v, const float* __restrict__ sB2,
    float* __restrict__ acc)
{
    float h2[32];
#pragma unroll
    for (int k = 0; k < 32; k++) h2[k] = sB2[k];
#pragma unroll 8
    for (int j = 0; j < 64; j++) {
        float h1 = fmaf(x1, sW1[64 + j], sB1[j]);
        if (USE_X0) h1 = fmaf(x0, sW1[j], h1);
        h1 = fmaxf(h1, 0.0f);
        const float4* row = sW2v + j * 8;
#pragma unroll
        for (int kk = 0; kk < 8; kk++) {
            float4 w4 = row[kk];
            h2[kk * 4 + 0] = fmaf(h1, w4.x, h2[kk * 4 + 0]);
            h2[kk * 4 + 1] = fmaf(h1, w4.y, h2[kk * 4 + 1]);
            h2[kk * 4 + 2] = fmaf(h1, w4.z, h2[kk * 4 + 2]);
            h2[kk * 4 + 3] = fmaf(h1, w4.w, h2[kk * 4 + 3]);
        }
    }
#pragma unroll
    for (int k = 0; k < 32; k++) acc[k] = fmaf(w, fmaxf(h2[k], 0.0f), acc[k]);
}

__global__ __launch_bounds__(TPB) void ph_main(
    const float* __restrict__ pc,   // [nB,14,3]
    const float* __restrict__ rb,   // [nB,3]
    const float* __restrict__ rd,   // [nB,3]
    const float* __restrict__ W1,   // [2,64]
    const float* __restrict__ b1,   // [64]
    const float* __restrict__ W2,   // [64,32]
    const float* __restrict__ b2,   // [32]
    float* __restrict__ outEuler,   // [nB]
    int nB)
{
    __shared__ float sPts[42 * (TPB + 1)];
    __shared__ float sW1[128];
    __shared__ float sB1[64];
    __shared__ __align__(16) float sW2[2048];
    __shared__ float sB2[32];
    __shared__ float sRed[(TPB / 32) * 36];

    const int tid = threadIdx.x;
    const int base = blockIdx.x * TPB;
    const int nLocal = min(TPB, nB - base);

    for (int i = tid; i < 128;  i += TPB) sW1[i] = W1[i];
    for (int i = tid; i < 64;   i += TPB) sB1[i] = b1[i];
    for (int i = tid; i < 2048; i += TPB) sW2[i] = W2[i];
    for (int i = tid; i < 32;   i += TPB) sB2[i] = b2[i];
    // cooperative, coalesced load of points into transposed shared layout
    for (int i = tid; i < 42 * nLocal; i += TPB) {
        int L = i / 42, c = i % 42;
        sPts[c * (TPB + 1) + L] = pc[(long long)base * 42 + i];
    }
    __syncthreads();

    float acc[32];
#pragma unroll
    for (int k = 0; k < 32; k++) acc[k] = 0.0f;
    float sp0 = 0.0f, plp0 = 0.0f, sp1 = 0.0f, plp1 = 0.0f;

    const int b = base + tid;
    if (tid < nLocal) {
        const float4* sW2v = (const float4*)sW2;
#define PT(i, c) sPts[((i) * 3 + (c)) * (TPB + 1) + tid]

        // dmax over all pairs (squared domain)
        float maxd2 = 0.0f;
        for (int i = 0; i < 14; i++) {
            float px = PT(i, 0), py = PT(i, 1), pz = PT(i, 2);
            for (int j = i + 1; j < 14; j++) {
                float dx = px - PT(j, 0), dy = py - PT(j, 1), dz = pz - PT(j, 2);
                float s = fmaxf(dx * dx + dy * dy + dz * dz, 1e-24f);
                maxd2 = fmaxf(maxd2, s);
            }
        }
        float dmax = sqrtf(maxd2);

        // Prim's MST in squared-distance domain (order-equivalent)
        float mind[14];
        {
            float px = PT(0, 0), py = PT(0, 1), pz = PT(0, 2);
            mind[0] = 1e30f;
#pragma unroll
            for (int k = 1; k < 14; k++) {
                float dx = px - PT(k, 0), dy = py - PT(k, 1), dz = pz - PT(k, 2);
                mind[k] = fmaxf(dx * dx + dy * dy + dz * dz, 1e-24f);
            }
        }
        unsigned intree = 1u;
        float m1 = 1e30f, m2 = 1e30f;  // two smallest MST edge weights (squared)
        for (int it = 0; it < 13; it++) {
            float best = mind[0]; int jsel = 0;
#pragma unroll
            for (int k = 1; k < 14; k++) {
                if (mind[k] < best) { best = mind[k]; jsel = k; }
            }
            if (best < m1) { m2 = m1; m1 = best; }
            else if (best < m2) { m2 = best; }
            float death = sqrtf(best);
            // dim-0 row: (0, death), weight 1
            mlp_accum<false>(0.0f, death, 1.0f, sW1, sB1, sW2v, sB2, acc);
            intree |= (1u << jsel);
#pragma unroll
            for (int k = 0; k < 14; k++) if (k == jsel) mind[k] = 1e30f;
            float qx = PT(jsel, 0), qy = PT(jsel, 1), qz = PT(jsel, 2);
#pragma unroll
            for (int k = 0; k < 14; k++) {
                if (!((intree >> k) & 1u)) {
                    float dx = qx - PT(k, 0), dy = qy - PT(k, 1), dz = qz - PT(k, 2);
                    float s = fmaxf(dx * dx + dy * dy + dz * dz, 1e-24f);
                    mind[k] = fminf(mind[k], s);
                }
            }
        }

        // dim-1 diagram (3 random features), rows weighted 13/3
        float bb[3], dd[3];
#pragma unroll
        for (int i = 0; i < 3; i++) {
            float rbv = rb[b * 3 + i];
            float rdv = rd[b * 3 + i];
            bb[i] = rbv * dmax * 0.3f;
            dd[i] = fmaf(rdv * dmax, 0.4f, bb[i]);
            mlp_accum<true>(bb[i], dd[i], 13.0f / 3.0f, sW1, sB1, sW2v, sB2, acc);
        }

        // entropy contributions (buggy-pair-axis semantics, faithful)
        float p = sqrtf(m2) - sqrtf(m1);
        if (p > 0.0f) { sp0 += p; plp0 += p * logf(p); }
        float pa = bb[1] - bb[0];
        if (pa > 0.0f) { sp1 += pa; plp1 += pa * logf(pa); }
        float pb2 = dd[1] - dd[0];
        if (pb2 > 0.0f) { sp1 += pb2; plp1 += pb2 * logf(pb2); }

        outEuler[b] = 10.0f;  // betti0 - betti1 = 13 - 3
#undef PT
    }

    // block reduction: warp shuffle, then cross-warp in shared, 36 atomics/block
    const unsigned FULL = 0xffffffffu;
#pragma unroll
    for (int k = 0; k < 32; k++) {
        float v = acc[k];
        v += __shfl_down_sync(FULL, v, 16);
        v += __shfl_down_sync(FULL, v, 8);
        v += __shfl_down_sync(FULL, v, 4);
        v += __shfl_down_sync(FULL, v, 2);
        v += __shfl_down_sync(FULL, v, 1);
        acc[k] = v;
    }
    float sc[4] = {sp0, plp0, sp1, plp1};
#pragma unroll
    for (int k = 0; k < 4; k++) {
        float v = sc[k];
        v += __shfl_down_sync(FULL, v, 16);
        v += __shfl_down_sync(FULL, v, 8);
        v += __shfl_down_sync(FULL, v, 4);
        v += __shfl_down_sync(FULL, v, 2);
        v += __shfl_down_sync(FULL, v, 1);
        sc[k] = v;
    }
    int lane = tid & 31, wrp = tid >> 5;
    if (lane == 0) {
#pragma unroll
        for (int k = 0; k < 32; k++) sRed[wrp * 36 + k] = acc[k];
#pragma unroll
        for (int k = 0; k < 4; k++) sRed[wrp * 36 + 32 + k] = sc[k];
    }
    __syncthreads();
    if (tid < 36) {
        float s = 0.0f;
#pragma unroll
        for (int w = 0; w < TPB / 32; w++) s += sRed[w * 36 + tid];
        atomicAdd(&g_acc[tid], s);
    }
}

__global__ void ph_final(const float* __restrict__ W3, const float* __restrict__ b3,
                         float* __restrict__ out, int nB)
{
    __shared__ float v[32];
    int t = threadIdx.x;
    if (t < 32) v[t] = g_acc[t] * (1.0f / (13.0f * (float)nB));
    __syncthreads();
    float s = 0.0f;
#pragma unroll
    for (int j = 0; j < 32; j++) s = fmaf(v[j], W3[j * F_OUT + t], s);
    out[t] = s + 2.0f * b3[t];
    if (t == 0) {
        float S0 = fmaxf(g_acc[32], 1e-30f), P0 = g_acc[33];
        float S1 = fmaxf(g_acc[34], 1e-30f), P1 = g_acc[35];
        // H = -sum (p/S) log(p/S + 1e-10) ~= log S - (sum p log p)/S  per diagram
        out[F_OUT + nB] = (logf(S0) - P0 / S0) + (logf(S1) - P1 / S1);
    }
}

extern "C" void kernel_launch(void* const* d_in, const int* in_sizes, int n_in,
                              void* d_out, int out_size)
{
    const float* pc = (const float*)d_in[0];
    const float* rb = (const float*)d_in[1];
    const float* rd = (const float*)d_in[2];
    const float* W1 = (const float*)d_in[3];
    const float* b1 = (const float*)d_in[4];
    const float* W2 = (const float*)d_in[5];
    const float* b2 = (const float*)d_in[6];
    const float* W3 = (const float*)d_in[7];
    const float* b3 = (const float*)d_in[8];
    int nB = in_sizes[0] / 42;  // B * 14 * 3 floats
    float* out = (float*)d_out; // [features(512) | euler(nB) | entropy(1)]

    ph_zero<<<1, 64>>>();
    int blocks = (nB + TPB - 1) / TPB;
    ph_main<<<blocks, TPB>>>(pc, rb, rd, W1, b1, W2, b2, out + F_OUT, nB);
    ph_final<<<1, 512>>>(W3, b3, out, nB);
}

// round 2
// speedup vs baseline: 1.3073x; 1.3073x over previous
#include <cuda_runtime.h>
#include <math.h>

#define TPB 128
#define F_OUT 512

// Global accumulators: [0..31] = weighted h2 sum, [32]=S0, [33]=sum p*log p (dim0),
// [34]=S1, [35]=sum p*log p (dim1)
__device__ float g_acc[36];

__global__ void ph_zero() {
    if (threadIdx.x < 36) g_acc[threadIdx.x] = 0.0f;
}

// ---- packed fp32x2 helpers (sm_100a FFMA2 path; ptxas never auto-fuses) ----
__device__ __forceinline__ unsigned long long pack2(float x) {
    unsigned long long r;
    asm("mov.b64 %0, {%1, %1};" : "=l"(r) : "f"(x));
    return r;
}
__device__ __forceinline__ unsigned long long ffma2(unsigned long long a,
                                                    unsigned long long b,
                                                    unsigned long long c) {
    unsigned long long d;
    asm("fma.rn.f32x2 %0, %1, %2, %3;" : "=l"(d) : "l"(a), "l"(b), "l"(c));
    return d;
}
__device__ __forceinline__ void unpack2(unsigned long long v, float& lo, float& hi) {
    asm("mov.b64 {%0, %1}, %2;" : "=f"(lo), "=f"(hi) : "l"(v));
}

// Two rows through the 2->64(relu)->32(relu) front end, h2 columns packed in
// f32x2 pairs. Both rows share one pass over W2 (halves LDS traffic).
// Accumulates wA*relu(h2_A) + wB*relu(h2_B) into acc[32].
template <bool USE_X0>
__device__ __forceinline__ void mlp2(
    float x0a, float x1a, float wA,
    float x0b, float x1b, float wB,
    const float* __restrict__ sW1, const float* __restrict__ sB1,
    const ulonglong2* __restrict__ sW2v,
    const unsigned long long* __restrict__ sB2p,
    float* __restrict__ acc)
{
    unsigned long long hA[16], hB[16];
#pragma unroll
    for (int t = 0; t < 16; t++) { unsigned long long b = sB2p[t]; hA[t] = b; hB[t] = b; }

#pragma unroll 8
    for (int j = 0; j < 64; j++) {
        float w1b = sW1[64 + j], b1j = sB1[j];
        float h1a = fmaf(x1a, w1b, b1j);
        float h1b = fmaf(x1b, w1b, b1j);
        if (USE_X0) {
            float w1a = sW1[j];
            h1a = fmaf(x0a, w1a, h1a);
            h1b = fmaf(x0b, w1a, h1b);
        }
        h1a = fmaxf(h1a, 0.0f);
        h1b = fmaxf(h1b, 0.0f);
        unsigned long long pa = pack2(h1a), pb = pack2(h1b);
        const ulonglong2* row = sW2v + j * 8;
#pragma unroll
        for (int t = 0; t < 8; t++) {
            ulonglong2 w2 = row[t];
            hA[2 * t]     = ffma2(pa, w2.x, hA[2 * t]);
            hB[2 * t]     = ffma2(pb, w2.x, hB[2 * t]);
            hA[2 * t + 1] = ffma2(pa, w2.y, hA[2 * t + 1]);
            hB[2 * t + 1] = ffma2(pb, w2.y, hB[2 * t + 1]);
        }
    }
#pragma unroll
    for (int t = 0; t < 16; t++) {
        float a0, a1, b0, b1v;
        unpack2(hA[t], a0, a1);
        unpack2(hB[t], b0, b1v);
        float s0 = fmaf(wA, fmaxf(a0, 0.0f), acc[2 * t]);
        acc[2 * t] = fmaf(wB, fmaxf(b0, 0.0f), s0);
        float s1 = fmaf(wA, fmaxf(a1, 0.0f), acc[2 * t + 1]);
        acc[2 * t + 1] = fmaf(wB, fmaxf(b1v, 0.0f), s1);
    }
}

__global__ __launch_bounds__(TPB) void ph_main(
    const float* __restrict__ pc,   // [nB,14,3]
    const float* __restrict__ rb,   // [nB,3]
    const float* __restrict__ rd,   // [nB,3]
    const float* __restrict__ W1,   // [2,64]
    const float* __restrict__ b1,   // [64]
    const float* __restrict__ W2,   // [64,32]
    const float* __restrict__ b2,   // [32]
    float* __restrict__ outEuler,   // [nB]
    int nB)
{
    __shared__ float sPts[42 * (TPB + 1)];
    __shared__ float sW1[128];
    __shared__ float sB1[64];
    __shared__ __align__(16) float sW2[2048];
    __shared__ __align__(16) float sB2[32];
    __shared__ float sRed[(TPB / 32) * 36];

    const int tid = threadIdx.x;
    const int base = blockIdx.x * TPB;
    const int nLocal = min(TPB, nB - base);

    for (int i = tid; i < 128;  i += TPB) sW1[i] = W1[i];
    for (int i = tid; i < 64;   i += TPB) sB1[i] = b1[i];
    for (int i = tid; i < 2048; i += TPB) sW2[i] = W2[i];
    for (int i = tid; i < 32;   i += TPB) sB2[i] = b2[i];
    for (int i = tid; i < 42 * nLocal; i += TPB) {
        int L = i / 42, c = i % 42;
        sPts[c * (TPB + 1) + L] = pc[(long long)base * 42 + i];
    }
    __syncthreads();

    float acc[32];
#pragma unroll
    for (int k = 0; k < 32; k++) acc[k] = 0.0f;
    float sp0 = 0.0f, plp0 = 0.0f, sp1 = 0.0f, plp1 = 0.0f;

    const int b = base + tid;
    if (tid < nLocal) {
        const ulonglong2* sW2v = (const ulonglong2*)sW2;
        const unsigned long long* sB2p = (const unsigned long long*)sB2;
#define PT(i, c) sPts[((i) * 3 + (c)) * (TPB + 1) + tid]

        // dmax over all pairs (squared domain)
        float maxd2 = 0.0f;
        for (int i = 0; i < 14; i++) {
            float px = PT(i, 0), py = PT(i, 1), pz = PT(i, 2);
            for (int j = i + 1; j < 14; j++) {
                float dx = px - PT(j, 0), dy = py - PT(j, 1), dz = pz - PT(j, 2);
                float s = fmaxf(dx * dx + dy * dy + dz * dz, 1e-24f);
                maxd2 = fmaxf(maxd2, s);
            }
        }
        float dmax = sqrtf(maxd2);

        // Prim's MST in squared-distance domain (order-equivalent).
        // Fully unrolled so xs[] stays in registers with static indexing.
        float xs0[13];
        float mind[14];
        {
            float px = PT(0, 0), py = PT(0, 1), pz = PT(0, 2);
            mind[0] = 1e30f;
#pragma unroll
            for (int k = 1; k < 14; k++) {
                float dx = px - PT(k, 0), dy = py - PT(k, 1), dz = pz - PT(k, 2);
                mind[k] = fmaxf(dx * dx + dy * dy + dz * dz, 1e-24f);
            }
        }
        unsigned intree = 1u;
        float m1 = 1e30f, m2 = 1e30f;  // two smallest MST edge weights (squared)
#pragma unroll
        for (int it = 0; it < 13; it++) {
            float best = mind[0]; int jsel = 0;
#pragma unroll
            for (int k = 1; k < 14; k++) {
                if (mind[k] < best) { best = mind[k]; jsel = k; }
            }
            if (best < m1) { m2 = m1; m1 = best; }
            else if (best < m2) { m2 = best; }
            xs0[it] = sqrtf(best);
            intree |= (1u << jsel);
#pragma unroll
            for (int k = 0; k < 14; k++) if (k == jsel) mind[k] = 1e30f;
            float qx = PT(jsel, 0), qy = PT(jsel, 1), qz = PT(jsel, 2);
#pragma unroll
            for (int k = 0; k < 14; k++) {
                if (!((intree >> k) & 1u)) {
                    float dx = qx - PT(k, 0), dy = qy - PT(k, 1), dz = qz - PT(k, 2);
                    float s = fmaxf(dx * dx + dy * dy + dz * dz, 1e-24f);
                    mind[k] = fminf(mind[k], s);
                }
            }
        }

        // dim-1 diagram (3 random features)
        float bb[3], dd[3];
#pragma unroll
        for (int i = 0; i < 3; i++) {
            float rbv = rb[b * 3 + i];
            float rdv = rd[b * 3 + i];
            bb[i] = rbv * dmax * 0.3f;
            dd[i] = fmaf(rdv * dmax, 0.4f, bb[i]);
        }

        // MLP: 13 dim-0 rows (x=(0,death), w=1) + 3 dim-1 rows (x=(bb,dd), w=13/3)
        const float W1WT = 13.0f / 3.0f;
        mlp2<false>(0.f, xs0[0],  1.f, 0.f, xs0[1],  1.f, sW1, sB1, sW2v, sB2p, acc);
        mlp2<false>(0.f, xs0[2],  1.f, 0.f, xs0[3],  1.f, sW1, sB1, sW2v, sB2p, acc);
        mlp2<false>(0.f, xs0[4],  1.f, 0.f, xs0[5],  1.f, sW1, sB1, sW2v, sB2p, acc);
        mlp2<false>(0.f, xs0[6],  1.f, 0.f, xs0[7],  1.f, sW1, sB1, sW2v, sB2p, acc);
        mlp2<false>(0.f, xs0[8],  1.f, 0.f, xs0[9],  1.f, sW1, sB1, sW2v, sB2p, acc);
        mlp2<false>(0.f, xs0[10], 1.f, 0.f, xs0[11], 1.f, sW1, sB1, sW2v, sB2p, acc);
        mlp2<true >(0.f, xs0[12], 1.f, bb[0], dd[0], W1WT, sW1, sB1, sW2v, sB2p, acc);
        mlp2<true >(bb[1], dd[1], W1WT, bb[2], dd[2], W1WT, sW1, sB1, sW2v, sB2p, acc);

        // entropy contributions (buggy-pair-axis semantics, faithful)
        float p = sqrtf(m2) - sqrtf(m1);
        if (p > 0.0f) { sp0 += p; plp0 += p * logf(p); }
        float pa = bb[1] - bb[0];
        if (pa > 0.0f) { sp1 += pa; plp1 += pa * logf(pa); }
        float pb2 = dd[1] - dd[0];
        if (pb2 > 0.0f) { sp1 += pb2; plp1 += pb2 * logf(pb2); }

        outEuler[b] = 10.0f;  // betti0 - betti1 = 13 - 3
#undef PT
    }

    // block reduction: warp shuffle, then cross-warp in shared, 36 atomics/block
    const unsigned FULL = 0xffffffffu;
#pragma unroll
    for (int k = 0; k < 32; k++) {
        float v = acc[k];
        v += __shfl_down_sync(FULL, v, 16);
        v += __shfl_down_sync(FULL, v, 8);
        v += __shfl_down_sync(FULL, v, 4);
        v += __shfl_down_sync(FULL, v, 2);
        v += __shfl_down_sync(FULL, v, 1);
        acc[k] = v;
    }
    float sc[4] = {sp0, plp0, sp1, plp1};
#pragma unroll
    for (int k = 0; k < 4; k++) {
        float v = sc[k];
        v += __shfl_down_sync(FULL, v, 16);
        v += __shfl_down_sync(FULL, v, 8);
        v += __shfl_down_sync(FULL, v, 4);
        v += __shfl_down_sync(FULL, v, 2);
        v += __shfl_down_sync(FULL, v, 1);
        sc[k] = v;
    }
    int lane = tid & 31, wrp = tid >> 5;
    if (lane == 0) {
#pragma unroll
        for (int k = 0; k < 32; k++) sRed[wrp * 36 + k] = acc[k];
#pragma unroll
        for (int k = 0; k < 4; k++) sRed[wrp * 36 + 32 + k] = sc[k];
    }
    __syncthreads();
    if (tid < 36) {
        float s = 0.0f;
#pragma unroll
        for (int w = 0; w < TPB / 32; w++) s += sRed[w * 36 + tid];
        atomicAdd(&g_acc[tid], s);
    }
}

__global__ void ph_final(const float* __restrict__ W3, const float* __restrict__ b3,
                         float* __restrict__ out, int nB)
{
    __shared__ float v[32];
    int t = threadIdx.x;
    if (t < 32) v[t] = g_acc[t] * (1.0f / (13.0f * (float)nB));
    __syncthreads();
    float s = 0.0f;
#pragma unroll
    for (int j = 0; j < 32; j++) s = fmaf(v[j], W3[j * F_OUT + t], s);
    out[t] = s + 2.0f * b3[t];
    if (t == 0) {
        float S0 = fmaxf(g_acc[32], 1e-30f), P0 = g_acc[33];
        float S1 = fmaxf(g_acc[34], 1e-30f), P1 = g_acc[35];
        out[F_OUT + nB] = (logf(S0) - P0 / S0) + (logf(S1) - P1 / S1);
    }
}

extern "C" void kernel_launch(void* const* d_in, const int* in_sizes, int n_in,
                              void* d_out, int out_size)
{
    const float* pc = (const float*)d_in[0];
    const float* rb = (const float*)d_in[1];
    const float* rd = (const float*)d_in[2];
    const float* W1 = (const float*)d_in[3];
    const float* b1 = (const float*)d_in[4];
    const float* W2 = (const float*)d_in[5];
    const float* b2 = (const float*)d_in[6];
    const float* W3 = (const float*)d_in[7];
    const float* b3 = (const float*)d_in[8];
    int nB = in_sizes[0] / 42;  // B * 14 * 3 floats
    float* out = (float*)d_out; // [features(512) | euler(nB) | entropy(1)]

    ph_zero<<<1, 64>>>();
    int blocks = (nB + TPB - 1) / TPB;
    ph_main<<<blocks, TPB>>>(pc, rb, rd, W1, b1, W2, b2, out + F_OUT, nB);
    ph_final<<<1, 512>>>(W3, b3, out, nB);
}

// round 4
// speedup vs baseline: 3.0180x; 2.3086x over previous
#include <cuda_runtime.h>
#include <math.h>

#define TPB 128
#define F_OUT 512
#define SEGSTRIDE 68
#define SENT 1e30f

// dynamic-shared layout offsets (floats) for ph_main_table
#define OFF_PTS   0
#define N_PTS     (42 * (TPB + 1))          // 5418 floats
#define OFF_TAB0  5420                      // 16B-aligned
#define OFF_TAB1  (OFF_TAB0 + 65 * SEGSTRIDE)   // +4420
#define OFF_S0    (OFF_TAB1 + 65 * SEGSTRIDE)
#define OFF_S1    (OFF_S0 + 64)
#define OFF_B2    (OFF_S1 + 64)
#define OFF_RED   (OFF_B2 + 32)
#define DYN_FLOATS (OFF_RED + (TPB / 32) * 36)
#define DYN_BYTES  (DYN_FLOATS * 4)

// Global accumulators: [0..31] = weighted h2 sum, [32]=S0, [33]=sum p*log p (dim0),
// [34]=S1, [35]=sum p*log p (dim1)
__device__ float g_acc[36];
__device__ int   g_flag;       // 1 => b1==0 && b2==0 (table path valid)
__device__ float g_T0[64];     // sorted breakpoints, dim-0 (death axis)
__device__ float g_T1[64];     // sorted breakpoints, dim-1 (ratio axis)
__device__ float g_tab0[65 * SEGSTRIDE];  // per-seg: A[32] | B[32] | pad
__device__ float g_tab1[65 * SEGSTRIDE];  // per-seg: P[32] | Q[32] | pad

// ---------------- setup 1: flag, breakpoints, rank-sort ----------------
__global__ void ph_setup1(const float* __restrict__ W1, const float* __restrict__ b1,
                          const float* __restrict__ b2)
{
    __shared__ float sK0[64], sK1[64];
    __shared__ int sFlag;
    int t = threadIdx.x;
    if (t < 36) g_acc[t] = 0.0f;
    if (t == 0) sFlag = 1;
    __syncthreads();
    if (t < 64 && b1[t] != 0.0f) sFlag = 0;
    if (t < 32 && b2[t] != 0.0f) sFlag = 0;
    if (t < 64) {
        float al = W1[64 + t], be = b1[t];
        float k0 = -be / al;
        if (!(al != 0.0f) || !(k0 > 0.0f) || !(k0 < SENT)) k0 = SENT;
        sK0[t] = k0;
        float w0 = W1[t], w1 = W1[64 + t];
        float k1 = -w0 / w1;
        if (!(w1 != 0.0f) || !(k1 > 0.0f) || !(k1 < SENT)) k1 = SENT;
        sK1[t] = k1;
    }
    __syncthreads();
    if (t < 64) {
        float k = sK0[t]; int r = 0;
        for (int i = 0; i < 64; i++) { float ki = sK0[i]; r += (ki < k) || (ki == k && i < t); }
        g_T0[r] = k;
    } else if (t < 128) {
        int j = t - 64;
        float k = sK1[j]; int r = 0;
        for (int i = 0; i < 64; i++) { float ki = sK1[i]; r += (ki < k) || (ki == k && i < j); }
        g_T1[r] = k;
    }
    __syncthreads();
    if (t == 0) g_flag = sFlag;
}

// ---------------- setup 2: per-segment linear tables ----------------
// grid = 130 blocks (2 tables x 65 segments), 32 threads (one per output col)
__global__ void ph_setup2(const float* __restrict__ W1, const float* __restrict__ b1,
                          const float* __restrict__ W2, const float* __restrict__ b2)
{
    int table = blockIdx.x / 65;
    int seg   = blockIdx.x % 65;
    const float* T = table ? g_T1 : g_T0;
    float lo = seg ? T[seg - 1] : 0.0f;
    float hi = (seg < 64) ? T[seg] : 1.5e30f;
    float d_rep;
    if (seg == 0)         d_rep = (hi >= 1e29f) ? 1.0f : 0.5f * hi;
    else if (hi >= 1e29f) d_rep = lo * 2.0f;
    else                  d_rep = 0.5f * (lo + hi);

    int k = threadIdx.x;
    float A = 0.0f;
    float B = table ? 0.0f : b2[k];
    for (int j = 0; j < 64; j++) {
        float ca, cb, act;
        if (table == 0) { float al = W1[64 + j], be = b1[j]; act = fmaf(al, d_rep, be); ca = al; cb = be; }
        else            { float w0 = W1[j], w1 = W1[64 + j]; act = fmaf(w1, d_rep, w0); ca = w0; cb = w1; }
        if (act > 0.0f) {
            float w = W2[j * 32 + k];
            A = fmaf(ca, w, A);
            B = fmaf(cb, w, B);
        }
    }
    float* tab = table ? g_tab1 : g_tab0;
    tab[seg * SEGSTRIDE + k]      = A;
    tab[seg * SEGSTRIDE + 32 + k] = B;
}

// lower-bound count over 64 sorted keys (shared), returns 0..64
__device__ __forceinline__ int seg_search(const float* __restrict__ keys, float d)
{
    int pos = 0;
#pragma unroll
    for (int w = 32; w >= 1; w >>= 1)
        if (keys[pos + w - 1] < d) pos += w;
    if (keys[pos] < d) pos++;
    return pos;
}

// ---------------- main (table path, requires g_flag==1) ----------------
__global__ __launch_bounds__(TPB) void ph_main_table(
    const float* __restrict__ pc, const float* __restrict__ rb, const float* __restrict__ rd,
    const float* __restrict__ b2, float* __restrict__ outEuler, int nB)
{
    if (g_flag == 0) return;

    extern __shared__ __align__(16) float dyn[];
    float* sPts  = dyn + OFF_PTS;
    float* sTab0 = dyn + OFF_TAB0;
    float* sTab1 = dyn + OFF_TAB1;
    float* sS0   = dyn + OFF_S0;
    float* sS1   = dyn + OFF_S1;
    float* sB2   = dyn + OFF_B2;
    float* sRed  = dyn + OFF_RED;

    const int tid = threadIdx.x;
    const int base = blockIdx.x * TPB;
    const int nLocal = min(TPB, nB - base);

    for (int i = tid; i < 65 * SEGSTRIDE; i += TPB) { sTab0[i] = g_tab0[i]; sTab1[i] = g_tab1[i]; }
    if (tid < 64) { sS0[tid] = g_T0[tid]; sS1[tid] = g_T1[tid]; }
    if (tid < 32) sB2[tid] = b2[tid];
    for (int i = tid; i < 42 * nLocal; i += TPB) {
        int L = i / 42, c = i % 42;
        sPts[c * (TPB + 1) + L] = pc[(long long)base * 42 + i];
    }
    __syncthreads();

    float acc[32];
#pragma unroll
    for (int k = 0; k < 32; k++) acc[k] = 0.0f;
    float sp0 = 0.0f, plp0 = 0.0f, sp1 = 0.0f, plp1 = 0.0f;

    const int b = base + tid;
    if (tid < nLocal) {
#define PT(i, c) sPts[((i) * 3 + (c)) * (TPB + 1) + tid]
        // dmax over all pairs (squared domain)
        float maxd2 = 0.0f;
        for (int i = 0; i < 14; i++) {
            float px = PT(i, 0), py = PT(i, 1), pz = PT(i, 2);
            for (int j = i + 1; j < 14; j++) {
                float dx = px - PT(j, 0), dy = py - PT(j, 1), dz = pz - PT(j, 2);
                float s = fmaxf(dx * dx + dy * dy + dz * dz, 1e-24f);
                maxd2 = fmaxf(maxd2, s);
            }
        }
        float dmax = sqrtf(maxd2);

        // Prim's MST in squared-distance domain (order-equivalent)
        float xs0[13];
        float mind[14];
        {
            float px = PT(0, 0), py = PT(0, 1), pz = PT(0, 2);
            mind[0] = 1e30f;
#pragma unroll
            for (int k = 1; k < 14; k++) {
                float dx = px - PT(k, 0), dy = py - PT(k, 1), dz = pz - PT(k, 2);
                mind[k] = fmaxf(dx * dx + dy * dy + dz * dz, 1e-24f);
            }
        }
        unsigned intree = 1u;
        float m1 = 1e30f, m2 = 1e30f;
#pragma unroll
        for (int it = 0; it < 13; it++) {
            float best = mind[0]; int jsel = 0;
#pragma unroll
            for (int k = 1; k < 14; k++) {
                if (mind[k] < best) { best = mind[k]; jsel = k; }
            }
            if (best < m1) { m2 = m1; m1 = best; }
            else if (best < m2) { m2 = best; }
            xs0[it] = sqrtf(best);
            intree |= (1u << jsel);
#pragma unroll
            for (int k = 0; k < 14; k++) if (k == jsel) mind[k] = 1e30f;
            float qx = PT(jsel, 0), qy = PT(jsel, 1), qz = PT(jsel, 2);
#pragma unroll
            for (int k = 0; k < 14; k++) {
                if (!((intree >> k) & 1u)) {
                    float dx = qx - PT(k, 0), dy = qy - PT(k, 1), dz = qz - PT(k, 2);
                    float s = fmaxf(dx * dx + dy * dy + dz * dz, 1e-24f);
                    mind[k] = fminf(mind[k], s);
                }
            }
        }

        // dim-0 rows via 1-D segment table: h2 = d*A + B
#pragma unroll
        for (int it = 0; it < 13; it++) {
            float d = xs0[it];
            int pos = seg_search(sS0, d);
            const float4* Ap = (const float4*)(sTab0 + pos * SEGSTRIDE);
            const float4* Bp = (const float4*)(sTab0 + pos * SEGSTRIDE + 32);
#pragma unroll
            for (int t4 = 0; t4 < 8; t4++) {
                float4 a4 = Ap[t4], b4 = Bp[t4];
                acc[t4 * 4 + 0] += fmaxf(fmaf(d, a4.x, b4.x), 0.0f);
                acc[t4 * 4 + 1] += fmaxf(fmaf(d, a4.y, b4.y), 0.0f);
                acc[t4 * 4 + 2] += fmaxf(fmaf(d, a4.z, b4.z), 0.0f);
                acc[t4 * 4 + 3] += fmaxf(fmaf(d, a4.w, b4.w), 0.0f);
            }
        }

        // dim-1 rows via ratio-segment table: h2 = x0*P + x1*Q + b2
        float bb[3], dd[3];
#pragma unroll
        for (int i = 0; i < 3; i++) {
            float rbv = rb[b * 3 + i];
            float rdv = rd[b * 3 + i];
            bb[i] = rbv * dmax * 0.3f;
            dd[i] = fmaf(rdv * dmax, 0.4f, bb[i]);
        }
        const float W1WT = 13.0f / 3.0f;
#pragma unroll
        for (int i = 0; i < 3; i++) {
            float x0 = bb[i], x1 = dd[i];
            float r = x1 / x0;  // inf if x0==0 -> maps to last segment
            int pos = seg_search(sS1, r);
            const float4* Pp = (const float4*)(sTab1 + pos * SEGSTRIDE);
            const float4* Qp = (const float4*)(sTab1 + pos * SEGSTRIDE + 32);
            const float4* B2p = (const float4*)sB2;
#pragma unroll
            for (int t4 = 0; t4 < 8; t4++) {
                float4 p4 = Pp[t4], q4 = Qp[t4], c4 = B2p[t4];
                float h0 = fmaf(x0, p4.x, fmaf(x1, q4.x, c4.x));
                float h1 = fmaf(x0, p4.y, fmaf(x1, q4.y, c4.y));
                float h2v = fmaf(x0, p4.z, fmaf(x1, q4.z, c4.z));
                float h3 = fmaf(x0, p4.w, fmaf(x1, q4.w, c4.w));
                acc[t4 * 4 + 0] = fmaf(W1WT, fmaxf(h0, 0.0f), acc[t4 * 4 + 0]);
                acc[t4 * 4 + 1] = fmaf(W1WT, fmaxf(h1, 0.0f), acc[t4 * 4 + 1]);
                acc[t4 * 4 + 2] = fmaf(W1WT, fmaxf(h2v, 0.0f), acc[t4 * 4 + 2]);
                acc[t4 * 4 + 3] = fmaf(W1WT, fmaxf(h3, 0.0f), acc[t4 * 4 + 3]);
            }
        }

        // entropy contributions (buggy-pair-axis semantics, faithful)
        float p = sqrtf(m2) - sqrtf(m1);
        if (p > 0.0f) { sp0 += p; plp0 += p * logf(p); }
        float pa = bb[1] - bb[0];
        if (pa > 0.0f) { sp1 += pa; plp1 += pa * logf(pa); }
        float pb2 = dd[1] - dd[0];
        if (pb2 > 0.0f) { sp1 += pb2; plp1 += pb2 * logf(pb2); }

        outEuler[b] = 10.0f;
#undef PT
    }

    // block reduction
    const unsigned FULL = 0xffffffffu;
#pragma unroll
    for (int k = 0; k < 32; k++) {
        float v = acc[k];
        v += __shfl_down_sync(FULL, v, 16);
        v += __shfl_down_sync(FULL, v, 8);
        v += __shfl_down_sync(FULL, v, 4);
        v += __shfl_down_sync(FULL, v, 2);
        v += __shfl_down_sync(FULL, v, 1);
        acc[k] = v;
    }
    float sc[4] = {sp0, plp0, sp1, plp1};
#pragma unroll
    for (int k = 0; k < 4; k++) {
        float v = sc[k];
        v += __shfl_down_sync(FULL, v, 16);
        v += __shfl_down_sync(FULL, v, 8);
        v += __shfl_down_sync(FULL, v, 4);
        v += __shfl_down_sync(FULL, v, 2);
        v += __shfl_down_sync(FULL, v, 1);
        sc[k] = v;
    }
    int lane = tid & 31, wrp = tid >> 5;
    if (lane == 0) {
#pragma unroll
        for (int k = 0; k < 32; k++) sRed[wrp * 36 + k] = acc[k];
#pragma unroll
        for (int k = 0; k < 4; k++) sRed[wrp * 36 + 32 + k] = sc[k];
    }
    __syncthreads();
    if (tid < 36) {
        float s = 0.0f;
#pragma unroll
        for (int w = 0; w < TPB / 32; w++) s += sRed[w * 36 + tid];
        atomicAdd(&g_acc[tid], s);
    }
}

// ---------------- general fallback (runs only if g_flag==0) ----------------
__device__ __forceinline__ unsigned long long pack2(float x) {
    unsigned long long r;
    asm("mov.b64 %0, {%1, %1};" : "=l"(r) : "f"(x));
    return r;
}
__device__ __forceinline__ unsigned long long ffma2(unsigned long long a,
                                                    unsigned long long b,
                                                    unsigned long long c) {
    unsigned long long d;
    asm("fma.rn.f32x2 %0, %1, %2, %3;" : "=l"(d) : "l"(a), "l"(b), "l"(c));
    return d;
}
__device__ __forceinline__ void unpack2(unsigned long long v, float& lo, float& hi) {
    asm("mov.b64 {%0, %1}, %2;" : "=f"(lo), "=f"(hi) : "l"(v));
}

template <bool USE_X0>
__device__ __forceinline__ void mlp2(
    float x0a, float x1a, float wA,
    float x0b, float x1b, float wB,
    const float* __restrict__ sW1, const float* __restrict__ sB1,
    const ulonglong2* __restrict__ sW2v,
    const unsigned long long* __restrict__ sB2p,
    float* __restrict__ acc)
{
    unsigned long long hA[16], hB[16];
#pragma unroll
    for (int t = 0; t < 16; t++) { unsigned long long b = sB2p[t]; hA[t] = b; hB[t] = b; }
#pragma unroll 8
    for (int j = 0; j < 64; j++) {
        float w1b = sW1[64 + j], b1j = sB1[j];
        float h1a = fmaf(x1a, w1b, b1j);
        float h1b = fmaf(x1b, w1b, b1j);
        if (USE_X0) {
            float w1a = sW1[j];
            h1a = fmaf(x0a, w1a, h1a);
            h1b = fmaf(x0b, w1a, h1b);
        }
        h1a = fmaxf(h1a, 0.0f);
        h1b = fmaxf(h1b, 0.0f);
        unsigned long long pa = pack2(h1a), pb = pack2(h1b);
        const ulonglong2* row = sW2v + j * 8;
#pragma unroll
        for (int t = 0; t < 8; t++) {
            ulonglong2 w2 = row[t];
            hA[2 * t]     = ffma2(pa, w2.x, hA[2 * t]);
            hB[2 * t]     = ffma2(pb, w2.x, hB[2 * t]);
            hA[2 * t + 1] = ffma2(pa, w2.y, hA[2 * t + 1]);
            hB[2 * t + 1] = ffma2(pb, w2.y, hB[2 * t + 1]);
        }
    }
#pragma unroll
    for (int t = 0; t < 16; t++) {
        float a0, a1, b0, b1v;
        unpack2(hA[t], a0, a1);
        unpack2(hB[t], b0, b1v);
        float s0 = fmaf(wA, fmaxf(a0, 0.0f), acc[2 * t]);
        acc[2 * t] = fmaf(wB, fmaxf(b0, 0.0f), s0);
        float s1 = fmaf(wA, fmaxf(a1, 0.0f), acc[2 * t + 1]);
        acc[2 * t + 1] = fmaf(wB, fmaxf(b1v, 0.0f), s1);
    }
}

__global__ __launch_bounds__(TPB) void ph_main_general(
    const float* __restrict__ pc, const float* __restrict__ rb, const float* __restrict__ rd,
    const float* __restrict__ W1, const float* __restrict__ b1,
    const float* __restrict__ W2, const float* __restrict__ b2,
    float* __restrict__ outEuler, int nB)
{
    if (g_flag != 0) return;

    __shared__ float sPts[42 * (TPB + 1)];
    __shared__ float sW1[128];
    __shared__ float sB1[64];
    __shared__ __align__(16) float sW2[2048];
    __shared__ __align__(16) float sB2[32];
    __shared__ float sRed[(TPB / 32) * 36];

    const int tid = threadIdx.x;
    const int base = blockIdx.x * TPB;
    const int nLocal = min(TPB, nB - base);

    for (int i = tid; i < 128;  i += TPB) sW1[i] = W1[i];
    for (int i = tid; i < 64;   i += TPB) sB1[i] = b1[i];
    for (int i = tid; i < 2048; i += TPB) sW2[i] = W2[i];
    for (int i = tid; i < 32;   i += TPB) sB2[i] = b2[i];
    for (int i = tid; i < 42 * nLocal; i += TPB) {
        int L = i / 42, c = i % 42;
        sPts[c * (TPB + 1) + L] = pc[(long long)base * 42 + i];
    }
    __syncthreads();

    float acc[32];
#pragma unroll
    for (int k = 0; k < 32; k++) acc[k] = 0.0f;
    float sp0 = 0.0f, plp0 = 0.0f, sp1 = 0.0f, plp1 = 0.0f;

    const int b = base + tid;
    if (tid < nLocal) {
        const ulonglong2* sW2v = (const ulonglong2*)sW2;
        const unsigned long long* sB2p = (const unsigned long long*)sB2;
#define PT(i, c) sPts[((i) * 3 + (c)) * (TPB + 1) + tid]
        float maxd2 = 0.0f;
        for (int i = 0; i < 14; i++) {
            float px = PT(i, 0), py = PT(i, 1), pz = PT(i, 2);
            for (int j = i + 1; j < 14; j++) {
                float dx = px - PT(j, 0), dy = py - PT(j, 1), dz = pz - PT(j, 2);
                float s = fmaxf(dx * dx + dy * dy + dz * dz, 1e-24f);
                maxd2 = fmaxf(maxd2, s);
            }
        }
        float dmax = sqrtf(maxd2);

        float xs0[13];
        float mind[14];
        {
            float px = PT(0, 0), py = PT(0, 1), pz = PT(0, 2);
            mind[0] = 1e30f;
#pragma unroll
            for (int k = 1; k < 14; k++) {
                float dx = px - PT(k, 0), dy = py - PT(k, 1), dz = pz - PT(k, 2);
                mind[k] = fmaxf(dx * dx + dy * dy + dz * dz, 1e-24f);
            }
        }
        unsigned intree = 1u;
        float m1 = 1e30f, m2 = 1e30f;
#pragma unroll
        for (int it = 0; it < 13; it++) {
            float best = mind[0]; int jsel = 0;
#pragma unroll
            for (int k = 1; k < 14; k++) {
                if (mind[k] < best) { best = mind[k]; jsel = k; }
            }
            if (best < m1) { m2 = m1; m1 = best; }
            else if (best < m2) { m2 = best; }
            xs0[it] = sqrtf(best);
            intree |= (1u << jsel);
#pragma unroll
            for (int k = 0; k < 14; k++) if (k == jsel) mind[k] = 1e30f;
            float qx = PT(jsel, 0), qy = PT(jsel, 1), qz = PT(jsel, 2);
#pragma unroll
            for (int k = 0; k < 14; k++) {
                if (!((intree >> k) & 1u)) {
                    float dx = qx - PT(k, 0), dy = qy - PT(k, 1), dz = qz - PT(k, 2);
                    float s = fmaxf(dx * dx + dy * dy + dz * dz, 1e-24f);
                    mind[k] = fminf(mind[k], s);
                }
            }
        }

        float bb[3], dd[3];
#pragma unroll
        for (int i = 0; i < 3; i++) {
            float rbv = rb[b * 3 + i];
            float rdv = rd[b * 3 + i];
            bb[i] = rbv * dmax * 0.3f;
            dd[i] = fmaf(rdv * dmax, 0.4f, bb[i]);
        }

        const float W1WT = 13.0f / 3.0f;
        mlp2<false>(0.f, xs0[0],  1.f, 0.f, xs0[1],  1.f, sW1, sB1, sW2v, sB2p, acc);
        mlp2<false>(0.f, xs0[2],  1.f, 0.f, xs0[3],  1.f, sW1, sB1, sW2v, sB2p, acc);
        mlp2<false>(0.f, xs0[4],  1.f, 0.f, xs0[5],  1.f, sW1, sB1, sW2v, sB2p, acc);
        mlp2<false>(0.f, xs0[6],  1.f, 0.f, xs0[7],  1.f, sW1, sB1, sW2v, sB2p, acc);
        mlp2<false>(0.f, xs0[8],  1.f, 0.f, xs0[9],  1.f, sW1, sB1, sW2v, sB2p, acc);
        mlp2<false>(0.f, xs0[10], 1.f, 0.f, xs0[11], 1.f, sW1, sB1, sW2v, sB2p, acc);
        mlp2<true >(0.f, xs0[12], 1.f, bb[0], dd[0], W1WT, sW1, sB1, sW2v, sB2p, acc);
        mlp2<true >(bb[1], dd[1], W1WT, bb[2], dd[2], W1WT, sW1, sB1, sW2v, sB2p, acc);

        float p = sqrtf(m2) - sqrtf(m1);
        if (p > 0.0f) { sp0 += p; plp0 += p * logf(p); }
        float pa = bb[1] - bb[0];
        if (pa > 0.0f) { sp1 += pa; plp1 += pa * logf(pa); }
        float pb2 = dd[1] - dd[0];
        if (pb2 > 0.0f) { sp1 += pb2; plp1 += pb2 * logf(pb2); }

        outEuler[b] = 10.0f;
#undef PT
    }

    const unsigned FULL = 0xffffffffu;
#pragma unroll
    for (int k = 0; k < 32; k++) {
        float v = acc[k];
        v += __shfl_down_sync(FULL, v, 16);
        v += __shfl_down_sync(FULL, v, 8);
        v += __shfl_down_sync(FULL, v, 4);
        v += __shfl_down_sync(FULL, v, 2);
        v += __shfl_down_sync(FULL, v, 1);
        acc[k] = v;
    }
    float sc[4] = {sp0, plp0, sp1, plp1};
#pragma unroll
    for (int k = 0; k < 4; k++) {
        float v = sc[k];
        v += __shfl_down_sync(FULL, v, 16);
        v += __shfl_down_sync(FULL, v, 8);
        v += __shfl_down_sync(FULL, v, 4);
        v += __shfl_down_sync(FULL, v, 2);
        v += __shfl_down_sync(FULL, v, 1);
        sc[k] = v;
    }
    int lane = tid & 31, wrp = tid >> 5;
    if (lane == 0) {
#pragma unroll
        for (int k = 0; k < 32; k++) sRed[wrp * 36 + k] = acc[k];
#pragma unroll
        for (int k = 0; k < 4; k++) sRed[wrp * 36 + 32 + k] = sc[k];
    }
    __syncthreads();
    if (tid < 36) {
        float s = 0.0f;
#pragma unroll
        for (int w = 0; w < TPB / 32; w++) s += sRed[w * 36 + tid];
        atomicAdd(&g_acc[tid], s);
    }
}

__global__ void ph_final(const float* __restrict__ W3, const float* __restrict__ b3,
                         float* __restrict__ out, int nB)
{
    __shared__ float v[32];
    int t = threadIdx.x;
    if (t < 32) v[t] = g_acc[t] * (1.0f / (13.0f * (float)nB));
    __syncthreads();
    float s = 0.0f;
#pragma unroll
    for (int j = 0; j < 32; j++) s = fmaf(v[j], W3[j * F_OUT + t], s);
    out[t] = s + 2.0f * b3[t];
    if (t == 0) {
        float S0 = fmaxf(g_acc[32], 1e-30f), P0 = g_acc[33];
        float S1 = fmaxf(g_acc[34], 1e-30f), P1 = g_acc[35];
        out[F_OUT + nB] = (logf(S0) - P0 / S0) + (logf(S1) - P1 / S1);
    }
}

extern "C" void kernel_launch(void* const* d_in, const int* in_sizes, int n_in,
                              void* d_out, int out_size)
{
    const float* pc = (const float*)d_in[0];
    const float* rb = (const float*)d_in[1];
    const float* rd = (const float*)d_in[2];
    const float* W1 = (const float*)d_in[3];
    const float* b1 = (const float*)d_in[4];
    const float* W2 = (const float*)d_in[5];
    const float* b2 = (const float*)d_in[6];
    const float* W3 = (const float*)d_in[7];
    const float* b3 = (const float*)d_in[8];
    int nB = in_sizes[0] / 42;
    float* out = (float*)d_out;

    static int smem_set = 0;
    if (!smem_set) {
        cudaFuncSetAttribute(ph_main_table,
                             cudaFuncAttributeMaxDynamicSharedMemorySize, DYN_BYTES);
        smem_set = 1;
    }

    ph_setup1<<<1, 128>>>(W1, b1, b2);
    ph_setup2<<<130, 32>>>(W1, b1, W2, b2);
    int blocks = (nB + TPB - 1) / TPB;
    ph_main_table<<<blocks, TPB, DYN_BYTES>>>(pc, rb, rd, b2, out + F_OUT, nB);
    ph_main_general<<<blocks, TPB>>>(pc, rb, rd, W1, b1, W2, b2, out + F_OUT, nB);
    ph_final<<<1, 512>>>(W3, b3, out, nB);
}

// round 5
// speedup vs baseline: 4.9499x; 1.6401x over previous
#include <cuda_runtime.h>
#include <math.h>

#define TPB 128
#define F_OUT 512
#define SENT 1e30f
#define GEN_BLOCKS 222

// Global accumulators: [0..31] weighted h2 sum, [32]=S0, [33]=sum p log p (dim0),
// [34]=S1, [35]=sum p log p (dim1)
__device__ float g_acc[36];
__device__ int   g_flag;          // 1 => b1==0 && b2==0 (table path valid)
__device__ float g_T1[64];        // sorted ratio breakpoints (dim-1)
__device__ float g_Ar[32];        // relu(sum_j relu(alpha_j) W2[j][k])  (dim-0 closed form)
__device__ float g_tabT1[4224];   // transposed dim-1 tables: P at k*66+seg, Q at 2112+k*66+seg
__device__ unsigned g_ticket = 0;

// ---------------- fused setup: flag, breakpoints, sort, tables ----------------
__global__ void ph_setup(const float* __restrict__ W1, const float* __restrict__ b1,
                         const float* __restrict__ W2, const float* __restrict__ b2)
{
    __shared__ float sW1[128];
    __shared__ float sW2[2048];
    __shared__ float sK[64];
    __shared__ float sT[64];
    __shared__ int sFlag;
    int t = threadIdx.x;  // 1024 threads
    if (t < 36) g_acc[t] = 0.0f;
    if (t == 0) sFlag = 1;
    for (int i = t; i < 128; i += 1024) sW1[i] = W1[i];
    for (int i = t; i < 2048; i += 1024) sW2[i] = W2[i];
    __syncthreads();
    if (t < 64 && b1[t] != 0.0f) sFlag = 0;
    if (t < 32 && b2[t] != 0.0f) sFlag = 0;
    if (t < 64) {
        float w0 = sW1[t], w1 = sW1[64 + t];
        float k1 = -w0 / w1;
        if (!(w1 != 0.0f) || !(k1 > 0.0f) || !(k1 < SENT)) k1 = SENT;
        sK[t] = k1;
    }
    __syncthreads();
    if (t < 64) {
        float k = sK[t]; int r = 0;
        for (int i = 0; i < 64; i++) { float ki = sK[i]; r += (ki < k) || (ki == k && i < t); }
        sT[r] = k;
    }
    if (t < 32) {
        float A = 0.0f;
        for (int j = 0; j < 64; j++)
            A = fmaf(fmaxf(sW1[64 + j], 0.0f), sW2[j * 32 + t], A);
        g_Ar[t] = fmaxf(A, 0.0f);
    }
    __syncthreads();
    if (t < 64) g_T1[t] = sT[t];
    if (t == 0) g_flag = sFlag;
    // dim-1 segment tables, transposed layout
    for (int job = t; job < 65 * 32; job += 1024) {
        int seg = job >> 5, k = job & 31;
        float lo = seg ? sT[seg - 1] : 0.0f;
        float hi = (seg < 64) ? sT[seg] : 1.5e30f;
        float rrep;
        if (seg == 0)         rrep = (hi >= 1e29f) ? 1.0f : 0.5f * hi;
        else if (hi >= 1e29f) rrep = lo * 2.0f;
        else                  rrep = 0.5f * (lo + hi);
        float P = 0.0f, Q = 0.0f;
        for (int j = 0; j < 64; j++) {
            float w0 = sW1[j], w1 = sW1[64 + j];
            if (fmaf(w1, rrep, w0) > 0.0f) {
                float w2 = sW2[j * 32 + k];
                P = fmaf(w0, w2, P);
                Q = fmaf(w1, w2, Q);
            }
        }
        g_tabT1[k * 66 + seg]        = P;
        g_tabT1[2112 + k * 66 + seg] = Q;
    }
}

// lower-bound over 64 sorted keys in shared
__device__ __forceinline__ int seg_search(const float* __restrict__ keys, float d)
{
    int pos = 0;
#pragma unroll
    for (int w = 32; w >= 1; w >>= 1)
        if (keys[pos + w - 1] < d) pos += w;
    if (keys[pos] < d) pos++;
    return pos;
}

// shared finalize body (last block): features + entropy + ticket reset
__device__ __forceinline__ void ph_finalize(
    float* __restrict__ vsh, const float* __restrict__ W3, const float* __restrict__ b3,
    float* __restrict__ out, int nB, int tid)
{
    if (tid < 32) vsh[tid] = atomicAdd(&g_acc[tid], 0.0f) * (1.0f / (13.0f * (float)nB));
    __syncthreads();
    for (int o = tid; o < F_OUT; o += TPB) {
        float s = 0.0f;
#pragma unroll
        for (int j = 0; j < 32; j++) s = fmaf(vsh[j], W3[j * F_OUT + o], s);
        out[o] = s + 2.0f * b3[o];
    }
    if (tid == 0) {
        float S0 = fmaxf(atomicAdd(&g_acc[32], 0.0f), 1e-30f);
        float P0 = atomicAdd(&g_acc[33], 0.0f);
        float S1 = fmaxf(atomicAdd(&g_acc[34], 0.0f), 1e-30f);
        float P1 = atomicAdd(&g_acc[35], 0.0f);
        out[F_OUT + nB] = (logf(S0) - P0 / S0) + (logf(S1) - P1 / S1);
        g_ticket = 0u;
    }
}

// ---------------- main (table path, requires g_flag==1) ----------------
__global__ __launch_bounds__(TPB) void ph_main_table(
    const float* __restrict__ pc, const float* __restrict__ rb, const float* __restrict__ rd,
    const float* __restrict__ W3, const float* __restrict__ b3,
    float* __restrict__ out, int nB)
{
    if (g_flag == 0) return;

    __shared__ __align__(16) float uni[5420];   // pts (phase A) then tables (phase B)
    __shared__ float sS1[64];
    __shared__ __align__(16) float sAr[32];
    __shared__ float sRed[(TPB / 32) * 36];
    __shared__ unsigned sTicket;

    const int tid = threadIdx.x;
    const int base = blockIdx.x * TPB;
    const int nLocal = min(TPB, nB - base);
    float* outEuler = out + F_OUT;

    // phase A: stage points transposed; small tables
    for (int i = tid; i < 42 * nLocal; i += TPB) {
        int L = i / 42, c = i % 42;
        uni[c * (TPB + 1) + L] = pc[(long long)base * 42 + i];
    }
    if (tid < 64) sS1[tid] = g_T1[tid];
    if (tid < 32) sAr[tid] = g_Ar[tid];
    __syncthreads();

    const int b = base + tid;
    float sumd = 0.0f, m1 = SENT, m2 = SENT, dmax = 0.0f;
    float bb[3], dd[3];

    if (tid < nLocal) {
        // copy this thread's 42 coords to registers (static indexing after)
        float p[42];
#pragma unroll
        for (int i = 0; i < 42; i++) p[i] = uni[i * (TPB + 1) + tid];

        // dmax over all 91 pairs (registers only)
        float maxd2 = 0.0f;
#pragma unroll
        for (int i = 0; i < 14; i++) {
#pragma unroll
            for (int j = i + 1; j < 14; j++) {
                float dx = p[i * 3 + 0] - p[j * 3 + 0];
                float dy = p[i * 3 + 1] - p[j * 3 + 1];
                float dz = p[i * 3 + 2] - p[j * 3 + 2];
                maxd2 = fmaxf(maxd2, dx * dx + dy * dy + dz * dz);
            }
        }
        dmax = sqrtf(fmaxf(maxd2, 1e-24f));

        // Prim's MST in squared-distance domain
        float mind[14];
        mind[0] = SENT;
#pragma unroll
        for (int k = 1; k < 14; k++) {
            float dx = p[0] - p[k * 3 + 0];
            float dy = p[1] - p[k * 3 + 1];
            float dz = p[2] - p[k * 3 + 2];
            mind[k] = fmaxf(dx * dx + dy * dy + dz * dz, 1e-24f);
        }
        unsigned intree = 1u;
#pragma unroll
        for (int it = 0; it < 13; it++) {
            float best = mind[0]; int jsel = 0;
#pragma unroll
            for (int k = 1; k < 14; k++) {
                if (mind[k] < best) { best = mind[k]; jsel = k; }
            }
            if (best < m1) { m2 = m1; m1 = best; }
            else if (best < m2) { m2 = best; }
            sumd += sqrtf(best);
            intree |= (1u << jsel);
#pragma unroll
            for (int k = 0; k < 14; k++) if (k == jsel) mind[k] = SENT;
            float qx = uni[(jsel * 3 + 0) * (TPB + 1) + tid];
            float qy = uni[(jsel * 3 + 1) * (TPB + 1) + tid];
            float qz = uni[(jsel * 3 + 2) * (TPB + 1) + tid];
#pragma unroll
            for (int k = 1; k < 14; k++) {
                if (!((intree >> k) & 1u)) {
                    float dx = qx - p[k * 3 + 0];
                    float dy = qy - p[k * 3 + 1];
                    float dz = qz - p[k * 3 + 2];
                    mind[k] = fminf(mind[k], fmaxf(dx * dx + dy * dy + dz * dz, 1e-24f));
                }
            }
        }

        // dim-1 inputs
#pragma unroll
        for (int i = 0; i < 3; i++) {
            float rbv = rb[b * 3 + i];
            float rdv = rd[b * 3 + i];
            bb[i] = rbv * dmax * 0.3f;
            dd[i] = fmaf(rdv * dmax, 0.4f, bb[i]);
        }
    }

    // phase B: overwrite point staging with the dim-1 tables
    __syncthreads();
    for (int i = tid; i < 4224; i += TPB) uni[i] = g_tabT1[i];
    __syncthreads();

    float acc[32];
    float sp0 = 0.0f, plp0 = 0.0f, sp1 = 0.0f, plp1 = 0.0f;
    if (tid < nLocal) {
        // dim-0 closed form: sum_i relu(d_i * A) = (sum d_i) * relu(A)
        const float4* ar4 = (const float4*)sAr;
#pragma unroll
        for (int t4 = 0; t4 < 8; t4++) {
            float4 a = ar4[t4];
            acc[t4 * 4 + 0] = sumd * a.x;
            acc[t4 * 4 + 1] = sumd * a.y;
            acc[t4 * 4 + 2] = sumd * a.z;
            acc[t4 * 4 + 3] = sumd * a.w;
        }
        // dim-1 rows via transposed ratio-segment table (b2 == 0 in this path)
        const float W1WT = 13.0f / 3.0f;
#pragma unroll
        for (int i = 0; i < 3; i++) {
            float x0 = bb[i], x1 = dd[i];
            float r = x1 / x0;  // inf -> last segment; NaN (0/0) -> pos 0, values 0
            int pos = seg_search(sS1, r);
#pragma unroll
            for (int k = 0; k < 32; k++) {
                float hk = fmaf(x0, uni[k * 66 + pos], x1 * uni[2112 + k * 66 + pos]);
                acc[k] = fmaf(W1WT, fmaxf(hk, 0.0f), acc[k]);
            }
        }

        // entropy (buggy-pair-axis semantics, faithful)
        float pp = sqrtf(m2) - sqrtf(m1);
        if (pp > 0.0f) { sp0 += pp; plp0 += pp * logf(pp); }
        float pa = bb[1] - bb[0];
        if (pa > 0.0f) { sp1 += pa; plp1 += pa * logf(pa); }
        float pb2 = dd[1] - dd[0];
        if (pb2 > 0.0f) { sp1 += pb2; plp1 += pb2 * logf(pb2); }

        outEuler[b] = 10.0f;  // betti0 - betti1 = 13 - 3
    } else {
#pragma unroll
        for (int k = 0; k < 32; k++) acc[k] = 0.0f;
    }

    // block reduction -> 36 atomics
    const unsigned FULL = 0xffffffffu;
#pragma unroll
    for (int k = 0; k < 32; k++) {
        float v = acc[k];
        v += __shfl_down_sync(FULL, v, 16);
        v += __shfl_down_sync(FULL, v, 8);
        v += __shfl_down_sync(FULL, v, 4);
        v += __shfl_down_sync(FULL, v, 2);
        v += __shfl_down_sync(FULL, v, 1);
        acc[k] = v;
    }
    float sc[4] = {sp0, plp0, sp1, plp1};
#pragma unroll
    for (int k = 0; k < 4; k++) {
        float v = sc[k];
        v += __shfl_down_sync(FULL, v, 16);
        v += __shfl_down_sync(FULL, v, 8);
        v += __shfl_down_sync(FULL, v, 4);
        v += __shfl_down_sync(FULL, v, 2);
        v += __shfl_down_sync(FULL, v, 1);
        sc[k] = v;
    }
    int lane = tid & 31, wrp = tid >> 5;
    if (lane == 0) {
#pragma unroll
        for (int k = 0; k < 32; k++) sRed[wrp * 36 + k] = acc[k];
#pragma unroll
        for (int k = 0; k < 4; k++) sRed[wrp * 36 + 32 + k] = sc[k];
    }
    __syncthreads();
    if (tid < 36) {
        float s = 0.0f;
#pragma unroll
        for (int w = 0; w < TPB / 32; w++) s += sRed[w * 36 + tid];
        atomicAdd(&g_acc[tid], s);
    }

    // last-block finalize (replaces ph_final launch)
    __threadfence();
    __syncthreads();
    if (tid == 0) sTicket = atomicAdd(&g_ticket, 1u);
    __syncthreads();
    if (sTicket == (unsigned)(gridDim.x - 1))
        ph_finalize(sRed, W3, b3, out, nB, tid);
}

// ---------------- general fallback (runs only if g_flag==0) ----------------
__device__ __forceinline__ unsigned long long pack2(float x) {
    unsigned long long r;
    asm("mov.b64 %0, {%1, %1};" : "=l"(r) : "f"(x));
    return r;
}
__device__ __forceinline__ unsigned long long ffma2(unsigned long long a,
                                                    unsigned long long b,
                                                    unsigned long long c) {
    unsigned long long d;
    asm("fma.rn.f32x2 %0, %1, %2, %3;" : "=l"(d) : "l"(a), "l"(b), "l"(c));
    return d;
}
__device__ __forceinline__ void unpack2(unsigned long long v, float& lo, float& hi) {
    asm("mov.b64 {%0, %1}, %2;" : "=f"(lo), "=f"(hi) : "l"(v));
}

template <bool USE_X0>
__device__ __forceinline__ void mlp2(
    float x0a, float x1a, float wA,
    float x0b, float x1b, float wB,
    const float* __restrict__ sW1, const float* __restrict__ sB1,
    const ulonglong2* __restrict__ sW2v,
    const unsigned long long* __restrict__ sB2p,
    float* __restrict__ acc)
{
    unsigned long long hA[16], hB[16];
#pragma unroll
    for (int t = 0; t < 16; t++) { unsigned long long b = sB2p[t]; hA[t] = b; hB[t] = b; }
#pragma unroll 8
    for (int j = 0; j < 64; j++) {
        float w1b = sW1[64 + j], b1j = sB1[j];
        float h1a = fmaf(x1a, w1b, b1j);
        float h1b = fmaf(x1b, w1b, b1j);
        if (USE_X0) {
            float w1a = sW1[j];
            h1a = fmaf(x0a, w1a, h1a);
            h1b = fmaf(x0b, w1a, h1b);
        }
        h1a = fmaxf(h1a, 0.0f);
        h1b = fmaxf(h1b, 0.0f);
        unsigned long long pa = pack2(h1a), pb = pack2(h1b);
        const ulonglong2* row = sW2v + j * 8;
#pragma unroll
        for (int t = 0; t < 8; t++) {
            ulonglong2 w2 = row[t];
            hA[2 * t]     = ffma2(pa, w2.x, hA[2 * t]);
            hB[2 * t]     = ffma2(pb, w2.x, hB[2 * t]);
            hA[2 * t + 1] = ffma2(pa, w2.y, hA[2 * t + 1]);
            hB[2 * t + 1] = ffma2(pb, w2.y, hB[2 * t + 1]);
        }
    }
#pragma unroll
    for (int t = 0; t < 16; t++) {
        float a0, a1, b0, b1v;
        unpack2(hA[t], a0, a1);
        unpack2(hB[t], b0, b1v);
        float s0 = fmaf(wA, fmaxf(a0, 0.0f), acc[2 * t]);
        acc[2 * t] = fmaf(wB, fmaxf(b0, 0.0f), s0);
        float s1 = fmaf(wA, fmaxf(a1, 0.0f), acc[2 * t + 1]);
        acc[2 * t + 1] = fmaf(wB, fmaxf(b1v, 0.0f), s1);
    }
}

__global__ __launch_bounds__(TPB) void ph_main_general(
    const float* __restrict__ pc, const float* __restrict__ rb, const float* __restrict__ rd,
    const float* __restrict__ W1, const float* __restrict__ b1,
    const float* __restrict__ W2, const float* __restrict__ b2,
    const float* __restrict__ W3, const float* __restrict__ b3,
    float* __restrict__ out, int nB)
{
    if (g_flag != 0) return;

    __shared__ float sPts[42 * (TPB + 1)];
    __shared__ float sW1[128];
    __shared__ float sB1[64];
    __shared__ __align__(16) float sW2[2048];
    __shared__ __align__(16) float sB2[32];
    __shared__ float sRed[(TPB / 32) * 36];
    __shared__ unsigned sTicket;

    const int tid = threadIdx.x;
    float* outEuler = out + F_OUT;

    for (int i = tid; i < 128;  i += TPB) sW1[i] = W1[i];
    for (int i = tid; i < 64;   i += TPB) sB1[i] = b1[i];
    for (int i = tid; i < 2048; i += TPB) sW2[i] = W2[i];
    for (int i = tid; i < 32;   i += TPB) sB2[i] = b2[i];

    float acc[32];
#pragma unroll
    for (int k = 0; k < 32; k++) acc[k] = 0.0f;
    float sp0 = 0.0f, plp0 = 0.0f, sp1 = 0.0f, plp1 = 0.0f;

    for (int base = blockIdx.x * TPB; base < nB; base += gridDim.x * TPB) {
        const int nLocal = min(TPB, nB - base);
        __syncthreads();
        for (int i = tid; i < 42 * nLocal; i += TPB) {
            int L = i / 42, c = i % 42;
            sPts[c * (TPB + 1) + L] = pc[(long long)base * 42 + i];
        }
        __syncthreads();

        const int b = base + tid;
        if (tid < nLocal) {
            const ulonglong2* sW2v = (const ulonglong2*)sW2;
            const unsigned long long* sB2p = (const unsigned long long*)sB2;
#define PT(i, c) sPts[((i) * 3 + (c)) * (TPB + 1) + tid]
            float maxd2 = 0.0f;
            for (int i = 0; i < 14; i++) {
                float px = PT(i, 0), py = PT(i, 1), pz = PT(i, 2);
                for (int j = i + 1; j < 14; j++) {
                    float dx = px - PT(j, 0), dy = py - PT(j, 1), dz = pz - PT(j, 2);
                    float s = fmaxf(dx * dx + dy * dy + dz * dz, 1e-24f);
                    maxd2 = fmaxf(maxd2, s);
                }
            }
            float dmax = sqrtf(maxd2);

            float xs0[13];
            float mind[14];
            {
                float px = PT(0, 0), py = PT(0, 1), pz = PT(0, 2);
                mind[0] = SENT;
#pragma unroll
                for (int k = 1; k < 14; k++) {
                    float dx = px - PT(k, 0), dy = py - PT(k, 1), dz = pz - PT(k, 2);
                    mind[k] = fmaxf(dx * dx + dy * dy + dz * dz, 1e-24f);
                }
            }
            unsigned intree = 1u;
            float m1 = SENT, m2 = SENT;
#pragma unroll
            for (int it = 0; it < 13; it++) {
                float best = mind[0]; int jsel = 0;
#pragma unroll
                for (int k = 1; k < 14; k++) {
                    if (mind[k] < best) { best = mind[k]; jsel = k; }
                }
                if (best < m1) { m2 = m1; m1 = best; }
                else if (best < m2) { m2 = best; }
                xs0[it] = sqrtf(best);
                intree |= (1u << jsel);
#pragma unroll
                for (int k = 0; k < 14; k++) if (k == jsel) mind[k] = SENT;
                float qx = PT(jsel, 0), qy = PT(jsel, 1), qz = PT(jsel, 2);
#pragma unroll
                for (int k = 0; k < 14; k++) {
                    if (!((intree >> k) & 1u)) {
                        float dx = qx - PT(k, 0), dy = qy - PT(k, 1), dz = qz - PT(k, 2);
                        float s = fmaxf(dx * dx + dy * dy + dz * dz, 1e-24f);
                        mind[k] = fminf(mind[k], s);
                    }
                }
            }

            float bbv[3], ddv[3];
#pragma unroll
            for (int i = 0; i < 3; i++) {
                float rbv = rb[b * 3 + i];
                float rdv = rd[b * 3 + i];
                bbv[i] = rbv * dmax * 0.3f;
                ddv[i] = fmaf(rdv * dmax, 0.4f, bbv[i]);
            }

            const float W1WT = 13.0f / 3.0f;
            mlp2<false>(0.f, xs0[0],  1.f, 0.f, xs0[1],  1.f, sW1, sB1, sW2v, sB2p, acc);
            mlp2<false>(0.f, xs0[2],  1.f, 0.f, xs0[3],  1.f, sW1, sB1, sW2v, sB2p, acc);
            mlp2<false>(0.f, xs0[4],  1.f, 0.f, xs0[5],  1.f, sW1, sB1, sW2v, sB2p, acc);
            mlp2<false>(0.f, xs0[6],  1.f, 0.f, xs0[7],  1.f, sW1, sB1, sW2v, sB2p, acc);
            mlp2<false>(0.f, xs0[8],  1.f, 0.f, xs0[9],  1.f, sW1, sB1, sW2v, sB2p, acc);
            mlp2<false>(0.f, xs0[10], 1.f, 0.f, xs0[11], 1.f, sW1, sB1, sW2v, sB2p, acc);
            mlp2<true >(0.f, xs0[12], 1.f, bbv[0], ddv[0], W1WT, sW1, sB1, sW2v, sB2p, acc);
            mlp2<true >(bbv[1], ddv[1], W1WT, bbv[2], ddv[2], W1WT, sW1, sB1, sW2v, sB2p, acc);

            float pp = sqrtf(m2) - sqrtf(m1);
            if (pp > 0.0f) { sp0 += pp; plp0 += pp * logf(pp); }
            float pa = bbv[1] - bbv[0];
            if (pa > 0.0f) { sp1 += pa; plp1 += pa * logf(pa); }
            float pb2 = ddv[1] - ddv[0];
            if (pb2 > 0.0f) { sp1 += pb2; plp1 += pb2 * logf(pb2); }

            outEuler[b] = 10.0f;
#undef PT
        }
    }

    const unsigned FULL = 0xffffffffu;
#pragma unroll
    for (int k = 0; k < 32; k++) {
        float v = acc[k];
        v += __shfl_down_sync(FULL, v, 16);
        v += __shfl_down_sync(FULL, v, 8);
        v += __shfl_down_sync(FULL, v, 4);
        v += __shfl_down_sync(FULL, v, 2);
        v += __shfl_down_sync(FULL, v, 1);
        acc[k] = v;
    }
    float sc[4] = {sp0, plp0, sp1, plp1};
#pragma unroll
    for (int k = 0; k < 4; k++) {
        float v = sc[k];
        v += __shfl_down_sync(FULL, v, 16);
        v += __shfl_down_sync(FULL, v, 8);
        v += __shfl_down_sync(FULL, v, 4);
        v += __shfl_down_sync(FULL, v, 2);
        v += __shfl_down_sync(FULL, v, 1);
        sc[k] = v;
    }
    int lane = tid & 31, wrp = tid >> 5;
    __syncthreads();
    if (lane == 0) {
#pragma unroll
        for (int k = 0; k < 32; k++) sRed[wrp * 36 + k] = acc[k];
#pragma unroll
        for (int k = 0; k < 4; k++) sRed[wrp * 36 + 32 + k] = sc[k];
    }
    __syncthreads();
    if (tid < 36) {
        float s = 0.0f;
#pragma unroll
        for (int w = 0; w < TPB / 32; w++) s += sRed[w * 36 + tid];
        atomicAdd(&g_acc[tid], s);
    }

    __threadfence();
    __syncthreads();
    if (tid == 0) sTicket = atomicAdd(&g_ticket, 1u);
    __syncthreads();
    if (sTicket == (unsigned)(gridDim.x - 1))
        ph_finalize(sRed, W3, b3, out, nB, tid);
}

extern "C" void kernel_launch(void* const* d_in, const int* in_sizes, int n_in,
                              void* d_out, int out_size)
{
    const float* pc = (const float*)d_in[0];
    const float* rb = (const float*)d_in[1];
    const float* rd = (const float*)d_in[2];
    const float* W1 = (const float*)d_in[3];
    const float* b1 = (const float*)d_in[4];
    const float* W2 = (const float*)d_in[5];
    const float* b2 = (const float*)d_in[6];
    const float* W3 = (const float*)d_in[7];
    const float* b3 = (const float*)d_in[8];
    int nB = in_sizes[0] / 42;  // B * 14 * 3 floats
    float* out = (float*)d_out; // [features(512) | euler(nB) | entropy(1)]

    ph_setup<<<1, 1024>>>(W1, b1, W2, b2);
    int blocks = (nB + TPB - 1) / TPB;
    ph_main_table<<<blocks, TPB>>>(pc, rb, rd, W3, b3, out, nB);
    ph_main_general<<<GEN_BLOCKS, TPB>>>(pc, rb, rd, W1, b1, W2, b2, W3, b3, out, nB);
}